// round 11
// baseline (speedup 1.0000x reference)
#include <cuda_runtime.h>
#include <math.h>

// Gaussian-mixture splat renderer, forward-differenced along grid columns.
// R10 structure (SMEM-staged coalesced stores, packed k-pair math) with the
// FD recurrence split into independent EVEN/ODD pixel chains: each chain
// advances 2 pixels per dependent multiply, halving the serial backbone and
// doubling schedulable ILP.
//
// c = x_idx*H + y_idx ; px = x_idx/(W-1), py = y_idx/(H-1).
// Per Gaussian k (prescaled by SC = sqrt(0.5*log2 e)):
//   t0 = s10*py + (s00*px + C0),  t1 = s11*py + A1,  e_k = exp2(-(t0^2+t1^2))
// Single-step FD: e_{j+1} = e_j r_j,  r_{j+1} = r_j rr,  rr = exp2(-2h^2 a)
// Two-step chains: e_{j+2} = e_j * (r_j^2 rr);  Q <- Q * rr^4 per 2-px step.
// out = saturate( sum_k w_k e_k / max(1e-7, sum_k e_k) )

#define NK 4
#define PIX 32
#define THR 128          // 4 warps
#define WARPS 4
#define GM_EPS 1e-7f

typedef unsigned long long u64t;

__device__ __forceinline__ float ex2(float x) {
    float y; asm("ex2.approx.ftz.f32 %0, %1;" : "=f"(y) : "f"(x)); return y;
}
__device__ __forceinline__ u64t pk2(float lo, float hi) {
    u64t r; asm("mov.b64 %0, {%1, %2};" : "=l"(r) : "f"(lo), "f"(hi)); return r;
}
__device__ __forceinline__ void upk2(u64t v, float& lo, float& hi) {
    asm("mov.b64 {%0, %1}, %2;" : "=f"(lo), "=f"(hi) : "l"(v));
}
__device__ __forceinline__ u64t mul2(u64t a, u64t b) {
    u64t d; asm("mul.rn.f32x2 %0, %1, %2;" : "=l"(d) : "l"(a), "l"(b)); return d;
}
__device__ __forceinline__ u64t add2(u64t a, u64t b) {
    u64t d; asm("add.rn.f32x2 %0, %1, %2;" : "=l"(d) : "l"(a), "l"(b)); return d;
}
__device__ __forceinline__ u64t fma2(u64t a, u64t b, u64t c) {
    u64t d; asm("fma.rn.f32x2 %0, %1, %2, %3;" : "=l"(d) : "l"(a), "l"(b), "l"(c)); return d;
}

// ---------------------------------------------------------------------------
// Main kernel. Lane l of global-warp gw owns pixels [gw*1024 + 32l, +32).
// Requires H % 32 == 0 and HW % 4096 == 0.
// SMEM tile: write tw[9*l + g] (conflict-free), read tw[36*i + l + (l>>3)].
// ---------------------------------------------------------------------------
__global__ void __launch_bounds__(THR, 10) gmix_fd(
    const float* __restrict__ params,
    float* __restrict__ out,
    int H, int HW, float inv_wm1, float inv_hm1)
{
    __shared__ float4 tile[WARPS][288];   // 18432 B

    const int warp = threadIdx.x >> 5;
    const int lane = threadIdx.x & 31;
    const int gw   = blockIdx.x * WARPS + warp;
    const int n    = blockIdx.y;
    const int c0   = gw * (32 * PIX) + lane * PIX;
    if (c0 >= HW) return;

    const float4* p4 = reinterpret_cast<const float4*>(params + n * 28);
    const float4 MUX = __ldg(p4 + 0);
    const float4 MUY = __ldg(p4 + 1);
    const float4 WKV = __ldg(p4 + 2);
    const float4 SG0 = __ldg(p4 + 3);   // {s00, s01(ignored), s10, s11}
    const float4 SG1 = __ldg(p4 + 4);
    const float4 SG2 = __ldg(p4 + 5);
    const float4 SG3 = __ldg(p4 + 6);

    const float mux[NK] = {MUX.x, MUX.y, MUX.z, MUX.w};
    const float muy[NK] = {MUY.x, MUY.y, MUY.z, MUY.w};
    const float SC = 0.84932180f;       // sqrt(0.5 * log2 e)
    const float s00[NK] = {SG0.x * SC, SG1.x * SC, SG2.x * SC, SG3.x * SC};
    const float s10[NK] = {SG0.z * SC, SG1.z * SC, SG2.z * SC, SG3.z * SC};
    const float s11[NK] = {SG0.w * SC, SG1.w * SC, SG2.w * SC, SG3.w * SC};

    const int   x_idx = c0 / H;
    const int   y0    = c0 - x_idx * H;
    const float px    = (float)x_idx * inv_wm1;
    const float py0   = (float)y0 * inv_hm1;
    const float h     = inv_hm1;

    // Seed even/odd chains per Gaussian.
    float ee[NK], eo[NK], qe[NK], qo[NK], r4[NK];
#pragma unroll
    for (int k = 0; k < NK; k++) {
        const float C0  = -(s00[k] * mux[k] + s10[k] * muy[k]);
        const float A1  = -s11[k] * muy[k];
        const float a   = fmaf(s10[k], s10[k], s11[k] * s11[k]);
        const float w0n = -(h * h) * a;
        const float un  = -2.0f * h * s10[k];
        const float vn  = -2.0f * h * s11[k];
        const float rr  = ex2(w0n + w0n);

        const float a0 = fmaf(s00[k], px, C0);
        const float t0 = fmaf(s10[k], py0, a0);
        const float t1 = fmaf(s11[k], py0, A1);
        const float e0 = ex2(fmaf(-t0, t0, -t1 * t1));
        const float r0 = ex2(fmaf(un, t0, fmaf(vn, t1, w0n)));

        const float rr2 = rr * rr;
        ee[k] = e0;
        eo[k] = e0 * r0;                 // pixel 1
        qe[k] = r0 * r0 * rr;            // even-chain 2-step ratio
        qo[k] = qe[k] * rr2;             // odd-chain 2-step ratio
        r4[k] = rr2 * rr2;               // Q update per 2-step
    }

    // Packed state over k-pairs.
    u64t Ee01 = pk2(ee[0], ee[1]), Ee23 = pk2(ee[2], ee[3]);
    u64t Eo01 = pk2(eo[0], eo[1]), Eo23 = pk2(eo[2], eo[3]);
    u64t Qe01 = pk2(qe[0], qe[1]), Qe23 = pk2(qe[2], qe[3]);
    u64t Qo01 = pk2(qo[0], qo[1]), Qo23 = pk2(qo[2], qo[3]);
    const u64t R401 = pk2(r4[0], r4[1]), R423 = pk2(r4[2], r4[3]);
    const u64t W01  = pk2(WKV.x, WKV.y), W23  = pk2(WKV.z, WKV.w);

    float4* tw = tile[warp];

#pragma unroll
    for (int grp = 0; grp < PIX / 4; grp++) {
        float4 res;
        float* rp = &res.x;
#pragma unroll
        for (int pq = 0; pq < 2; pq++) {            // one iter = pixel pair
            if (!(grp == 0 && pq == 0)) {
                // Advance both chains by 2 pixels (independent backbones).
                Ee01 = mul2(Ee01, Qe01);  Ee23 = mul2(Ee23, Qe23);
                Eo01 = mul2(Eo01, Qo01);  Eo23 = mul2(Eo23, Qo23);
                Qe01 = mul2(Qe01, R401);  Qe23 = mul2(Qe23, R423);
                Qo01 = mul2(Qo01, R401);  Qo23 = mul2(Qo23, R423);
            }
            // Even pixel.
            {
                const u64t G2 = add2(Ee01, Ee23);
                const u64t A2 = fma2(W01, Ee01, mul2(W23, Ee23));
                float g0, g1, a0, a1;
                upk2(G2, g0, g1);
                upk2(A2, a0, a1);
                rp[2 * pq] = __saturatef(
                    __fdividef(a0 + a1, fmaxf(GM_EPS, g0 + g1)));
            }
            // Odd pixel.
            {
                const u64t G2 = add2(Eo01, Eo23);
                const u64t A2 = fma2(W01, Eo01, mul2(W23, Eo23));
                float g0, g1, a0, a1;
                upk2(G2, g0, g1);
                upk2(A2, a0, a1);
                rp[2 * pq + 1] = __saturatef(
                    __fdividef(a0 + a1, fmaxf(GM_EPS, g0 + g1)));
            }
        }
        tw[9 * lane + grp] = res;                  // STS.128, conflict-free
    }

    __syncwarp();

    // Coalesced drain: warp writes 8 x 512B contiguous chunks.
    float4* ob = reinterpret_cast<float4*>(out + (size_t)n * (size_t)HW
                                               + (size_t)gw * (32 * PIX));
#pragma unroll
    for (int i = 0; i < 8; i++) {
        ob[32 * i + lane] = tw[36 * i + lane + (lane >> 3)];
    }
}

// ---------------------------------------------------------------------------
// Fallback: per-pixel direct evaluation (odd shapes).
// ---------------------------------------------------------------------------
__global__ void __launch_bounds__(256) gmix_generic(
    const float* __restrict__ params,
    float* __restrict__ out,
    int H, int HW, float inv_wm1, float inv_hm1)
{
    const int n = blockIdx.y;
    const float* p = params + n * 28;
    float mux[NK], muy[NK], wkk[NK], s00[NK], s10[NK], s11[NK];
#pragma unroll
    for (int k = 0; k < NK; k++) {
        mux[k] = __ldg(p + k);        muy[k] = __ldg(p + 4 + k);
        wkk[k] = __ldg(p + 8 + k);
        s00[k] = __ldg(p + 12 + 4*k + 0);
        s10[k] = __ldg(p + 12 + 4*k + 2);
        s11[k] = __ldg(p + 12 + 4*k + 3);
    }
    const int c = blockIdx.x * blockDim.x + threadIdx.x;
    if (c >= HW) return;
    const int x_idx = c / H, y_idx = c - x_idx * H;
    const float px = (float)x_idx * inv_wm1, py = (float)y_idx * inv_hm1;
    float g = 0.0f, acc = 0.0f;
#pragma unroll
    for (int k = 0; k < NK; k++) {
        const float d0 = px - mux[k], d1 = py - muy[k];
        const float t0 = fmaf(s00[k], d0, s10[k] * d1);
        const float t1 = s11[k] * d1;
        const float e  = __expf(-0.5f * fmaf(t0, t0, t1 * t1));
        g += e;
        acc = fmaf(wkk[k], e, acc);
    }
    out[(size_t)n * (size_t)HW + c] =
        __saturatef(__fdividef(acc, fmaxf(GM_EPS, g)));
}

// ---------------------------------------------------------------------------
extern "C" void kernel_launch(void* const* d_in, const int* in_sizes, int n_in,
                              void* d_out, int out_size)
{
    int pi = 0;
    for (int i = 1; i < n_in; i++)
        if (in_sizes[i] > in_sizes[pi]) pi = i;
    const float* params = (const float*)d_in[pi];

    const int N  = in_sizes[pi] / 28;
    const int HW = out_size / N;
    int H = (int)(sqrt((double)HW) + 0.5);
    while (H > 1 && (HW % H) != 0) H--;
    const int W = HW / H;

    const float inv_wm1 = 1.0f / (float)(W - 1);
    const float inv_hm1 = 1.0f / (float)(H - 1);

    const int px_per_block = THR * PIX;   // 4096
    if ((H % PIX) == 0 && (HW % px_per_block) == 0) {
        dim3 grid(HW / px_per_block, N);
        gmix_fd<<<grid, THR>>>(params, (float*)d_out,
                               H, HW, inv_wm1, inv_hm1);
    } else {
        const int threads = 256;
        dim3 grid((HW + threads - 1) / threads, N);
        gmix_generic<<<grid, threads>>>(params, (float*)d_out,
                                        H, HW, inv_wm1, inv_hm1);
    }
}

// round 12
// speedup vs baseline: 1.0052x; 1.0052x over previous
#include <cuda_runtime.h>
#include <math.h>

// Gaussian-mixture splat renderer, forward-differenced along grid columns.
// R10 math (packed k-pair chains + packed epilogue) with the SMEM staging
// tile shrunk 18,432 -> 16,384 B via XOR swizzle (no pad rows): fits exactly
// 2 x 8KB SMEM granules so 12 CTAs/SM become resident (was 9 -> occ +50%).
//
// c = x_idx*H + y_idx ; px = x_idx/(W-1), py = y_idx/(H-1).
// Per Gaussian k (prescaled by SC = sqrt(0.5*log2 e)):
//   t0 = s10*py + (s00*px + C0),  t1 = s11*py + A1,  e_k = exp2(-(t0^2+t1^2))
// FD along a column: e <- e*r, r <- r*rr, rr = exp2(-2 h^2 (s10^2+s11^2))
// out = saturate( sum_k w_k e_k / max(1e-7, sum_k e_k) )

#define NK 4
#define PIX 32
#define THR 128          // 4 warps
#define WARPS 4
#define GM_EPS 1e-7f

typedef unsigned long long u64t;

__device__ __forceinline__ float ex2(float x) {
    float y; asm("ex2.approx.ftz.f32 %0, %1;" : "=f"(y) : "f"(x)); return y;
}
__device__ __forceinline__ u64t pk2(float lo, float hi) {
    u64t r; asm("mov.b64 %0, {%1, %2};" : "=l"(r) : "f"(lo), "f"(hi)); return r;
}
__device__ __forceinline__ void upk2(u64t v, float& lo, float& hi) {
    asm("mov.b64 {%0, %1}, %2;" : "=f"(lo), "=f"(hi) : "l"(v));
}
__device__ __forceinline__ u64t mul2(u64t a, u64t b) {
    u64t d; asm("mul.rn.f32x2 %0, %1, %2;" : "=l"(d) : "l"(a), "l"(b)); return d;
}
__device__ __forceinline__ u64t add2(u64t a, u64t b) {
    u64t d; asm("add.rn.f32x2 %0, %1, %2;" : "=l"(d) : "l"(a), "l"(b)); return d;
}
__device__ __forceinline__ u64t fma2(u64t a, u64t b, u64t c) {
    u64t d; asm("fma.rn.f32x2 %0, %1, %2, %3;" : "=l"(d) : "l"(a), "l"(b), "l"(c)); return d;
}

// ---------------------------------------------------------------------------
// Main kernel. Lane l of global-warp gw owns pixels [gw*1024 + 32l, +32).
// Requires H % 32 == 0 and HW % 4096 == 0.
//
// SMEM tile (per warp, 256 float4 = 4096 B, XOR-swizzled, no padding):
//   write:  tw[8*l + (g ^ (l & 7))]           g = group 0..7
//   read :  output float4 f = 32*i + l comes from producer lane lp = 4i+(l>>3),
//           slot g = l&7  ->  tw[8*lp + ((l&7) ^ (lp & 7))]
// Both access patterns hit 8 distinct float4-slots per 8-lane phase.
// ---------------------------------------------------------------------------
__global__ void __launch_bounds__(THR, 12) gmix_fd(
    const float* __restrict__ params,
    float* __restrict__ out,
    int H, int HW, float inv_wm1, float inv_hm1)
{
    __shared__ float4 tile[WARPS][256];   // 16384 B total

    const int warp = threadIdx.x >> 5;
    const int lane = threadIdx.x & 31;
    const int gw   = blockIdx.x * WARPS + warp;
    const int n    = blockIdx.y;
    const int c0   = gw * (32 * PIX) + lane * PIX;
    if (c0 >= HW) return;

    const float4* p4 = reinterpret_cast<const float4*>(params + n * 28);
    const float4 MUX = __ldg(p4 + 0);
    const float4 MUY = __ldg(p4 + 1);
    const float4 WKV = __ldg(p4 + 2);
    const float4 SG0 = __ldg(p4 + 3);   // {s00, s01(ignored), s10, s11}
    const float4 SG1 = __ldg(p4 + 4);
    const float4 SG2 = __ldg(p4 + 5);
    const float4 SG3 = __ldg(p4 + 6);

    const float mux[NK] = {MUX.x, MUX.y, MUX.z, MUX.w};
    const float muy[NK] = {MUY.x, MUY.y, MUY.z, MUY.w};
    const float SC = 0.84932180f;       // sqrt(0.5 * log2 e)
    const float s00[NK] = {SG0.x * SC, SG1.x * SC, SG2.x * SC, SG3.x * SC};
    const float s10[NK] = {SG0.z * SC, SG1.z * SC, SG2.z * SC, SG3.z * SC};
    const float s11[NK] = {SG0.w * SC, SG1.w * SC, SG2.w * SC, SG3.w * SC};

    const int   x_idx = c0 / H;
    const int   y0    = c0 - x_idx * H;
    const float px    = (float)x_idx * inv_wm1;
    const float py0   = (float)y0 * inv_hm1;
    const float h     = inv_hm1;

    // Derive FD constants, seed e and r at the first pixel of this run.
    float es[NK], rs[NK], rrs[NK];
#pragma unroll
    for (int k = 0; k < NK; k++) {
        const float C0  = -(s00[k] * mux[k] + s10[k] * muy[k]);
        const float A1  = -s11[k] * muy[k];
        const float a   = fmaf(s10[k], s10[k], s11[k] * s11[k]);
        const float w0n = -(h * h) * a;
        const float un  = -2.0f * h * s10[k];
        const float vn  = -2.0f * h * s11[k];
        rrs[k] = ex2(w0n + w0n);

        const float a0 = fmaf(s00[k], px, C0);
        const float t0 = fmaf(s10[k], py0, a0);
        const float t1 = fmaf(s11[k], py0, A1);
        es[k] = ex2(fmaf(-t0, t0, -t1 * t1));
        rs[k] = ex2(fmaf(un, t0, fmaf(vn, t1, w0n)));
    }

    // Packed chain state over k-pairs.
    u64t E01 = pk2(es[0], es[1]), E23 = pk2(es[2], es[3]);
    u64t R01 = pk2(rs[0], rs[1]), R23 = pk2(rs[2], rs[3]);
    const u64t RR01 = pk2(rrs[0], rrs[1]), RR23 = pk2(rrs[2], rrs[3]);
    const u64t W01  = pk2(WKV.x, WKV.y),   W23  = pk2(WKV.z, WKV.w);

    float4* tw = tile[warp];
    const int wslot = 8 * lane;       // base of this lane's 8 write slots

#pragma unroll
    for (int grp = 0; grp < PIX / 4; grp++) {
        float4 res;
        float* rp = &res.x;
#pragma unroll
        for (int q = 0; q < 4; q++) {
            if (!(grp == 0 && q == 0)) {
                E01 = mul2(E01, R01);
                E23 = mul2(E23, R23);
                R01 = mul2(R01, RR01);
                R23 = mul2(R23, RR23);
            }
            const u64t G2 = add2(E01, E23);
            const u64t A2 = fma2(W01, E01, mul2(W23, E23));
            float g0, g1, a0, a1;
            upk2(G2, g0, g1);
            upk2(A2, a0, a1);
            rp[q] = __saturatef(
                __fdividef(a0 + a1, fmaxf(GM_EPS, g0 + g1)));
        }
        tw[wslot + (grp ^ (lane & 7))] = res;      // STS.128, conflict-free
    }

    __syncwarp();

    // Coalesced drain: warp writes 8 x 512B contiguous chunks.
    float4* ob = reinterpret_cast<float4*>(out + (size_t)n * (size_t)HW
                                               + (size_t)gw * (32 * PIX));
#pragma unroll
    for (int i = 0; i < 8; i++) {
        const int lp = 4 * i + (lane >> 3);
        ob[32 * i + lane] = tw[8 * lp + ((lane & 7) ^ (lp & 7))];
    }
}

// ---------------------------------------------------------------------------
// Fallback: per-pixel direct evaluation (odd shapes).
// ---------------------------------------------------------------------------
__global__ void __launch_bounds__(256) gmix_generic(
    const float* __restrict__ params,
    float* __restrict__ out,
    int H, int HW, float inv_wm1, float inv_hm1)
{
    const int n = blockIdx.y;
    const float* p = params + n * 28;
    float mux[NK], muy[NK], wkk[NK], s00[NK], s10[NK], s11[NK];
#pragma unroll
    for (int k = 0; k < NK; k++) {
        mux[k] = __ldg(p + k);        muy[k] = __ldg(p + 4 + k);
        wkk[k] = __ldg(p + 8 + k);
        s00[k] = __ldg(p + 12 + 4*k + 0);
        s10[k] = __ldg(p + 12 + 4*k + 2);
        s11[k] = __ldg(p + 12 + 4*k + 3);
    }
    const int c = blockIdx.x * blockDim.x + threadIdx.x;
    if (c >= HW) return;
    const int x_idx = c / H, y_idx = c - x_idx * H;
    const float px = (float)x_idx * inv_wm1, py = (float)y_idx * inv_hm1;
    float g = 0.0f, acc = 0.0f;
#pragma unroll
    for (int k = 0; k < NK; k++) {
        const float d0 = px - mux[k], d1 = py - muy[k];
        const float t0 = fmaf(s00[k], d0, s10[k] * d1);
        const float t1 = s11[k] * d1;
        const float e  = __expf(-0.5f * fmaf(t0, t0, t1 * t1));
        g += e;
        acc = fmaf(wkk[k], e, acc);
    }
    out[(size_t)n * (size_t)HW + c] =
        __saturatef(__fdividef(acc, fmaxf(GM_EPS, g)));
}

// ---------------------------------------------------------------------------
extern "C" void kernel_launch(void* const* d_in, const int* in_sizes, int n_in,
                              void* d_out, int out_size)
{
    int pi = 0;
    for (int i = 1; i < n_in; i++)
        if (in_sizes[i] > in_sizes[pi]) pi = i;
    const float* params = (const float*)d_in[pi];

    const int N  = in_sizes[pi] / 28;
    const int HW = out_size / N;
    int H = (int)(sqrt((double)HW) + 0.5);
    while (H > 1 && (HW % H) != 0) H--;
    const int W = HW / H;

    const float inv_wm1 = 1.0f / (float)(W - 1);
    const float inv_hm1 = 1.0f / (float)(H - 1);

    const int px_per_block = THR * PIX;   // 4096
    if ((H % PIX) == 0 && (HW % px_per_block) == 0) {
        dim3 grid(HW / px_per_block, N);
        gmix_fd<<<grid, THR>>>(params, (float*)d_out,
                               H, HW, inv_wm1, inv_hm1);
    } else {
        const int threads = 256;
        dim3 grid((HW + threads - 1) / threads, N);
        gmix_generic<<<grid, threads>>>(params, (float*)d_out,
                                        H, HW, inv_wm1, inv_hm1);
    }
}